// round 1
// baseline (speedup 1.0000x reference)
#include <cuda_runtime.h>
#include <math.h>

#define BB 4
#define TT 1024
#define DD 1024
#define NN 16
#define MM (BB*TT)   // 4096

// ---------------- scratch (no allocations allowed) ----------------
__device__ float g_x1[MM*DD];   // u @ Win + b_in
__device__ float g_z [MM*DD];   // silu(u @ Wg + bg)
__device__ float g_x3[MM*DD];   // silu(conv(x1))
__device__ float g_dt[MM*DD];   // softplus(x3 @ Wdt + bdt)
__device__ float g_Bm[MM*NN];
__device__ float g_Cm[MM*NN];
__device__ float g_y [MM*DD];   // scan output * z

__device__ __forceinline__ float silu_f(float v) {
    return v / (1.f + __expf(-v));
}
__device__ __forceinline__ float softplus_f(float v) {
    return (v > 20.f) ? v : log1pf(__expf(v));
}

// ---------------- classic 128x128x8 fp32 SGEMM, 256 thr, 8x8/thread ----------------
// MODE 0: +bias, 1: silu(+bias), 2: softplus(+bias)
template<int MODE>
__global__ __launch_bounds__(256)
void sgemm128(const float* __restrict__ A, const float* __restrict__ B,
              const float* __restrict__ bias, float* __restrict__ C,
              int M, int N, int K)
{
    __shared__ float As[8][128];   // transposed A tile
    __shared__ float Bs[8][128];

    const int tid = threadIdx.x;
    const int bm = blockIdx.y, bn = blockIdx.x;
    const int tr = tid / 16;           // 0..15
    const int tc = tid % 16;           // 0..15

    const int arow = tid / 2;          // 0..127
    const int acol = (tid & 1) * 4;    // 0 or 4
    const int brow = tid / 32;         // 0..7
    const int bcol = (tid % 32) * 4;   // 0..124

    const float* Ab = A + (size_t)bm * 128 * K;
    const float* Bb = B + (size_t)bn * 128;

    float acc[8][8];
#pragma unroll
    for (int i = 0; i < 8; i++)
#pragma unroll
        for (int j = 0; j < 8; j++) acc[i][j] = 0.f;

    for (int k0 = 0; k0 < K; k0 += 8) {
        float4 a4 = *(const float4*)(Ab + (size_t)arow * K + k0 + acol);
        As[acol + 0][arow] = a4.x;
        As[acol + 1][arow] = a4.y;
        As[acol + 2][arow] = a4.z;
        As[acol + 3][arow] = a4.w;
        float4 b4 = *(const float4*)(Bb + (size_t)(k0 + brow) * N + bcol);
        *(float4*)&Bs[brow][bcol] = b4;
        __syncthreads();

#pragma unroll
        for (int k = 0; k < 8; k++) {
            float4 ra0 = *(const float4*)&As[k][tr * 8];
            float4 ra1 = *(const float4*)&As[k][tr * 8 + 4];
            float4 rb0 = *(const float4*)&Bs[k][tc * 8];
            float4 rb1 = *(const float4*)&Bs[k][tc * 8 + 4];
            float ra[8] = {ra0.x, ra0.y, ra0.z, ra0.w, ra1.x, ra1.y, ra1.z, ra1.w};
            float rb[8] = {rb0.x, rb0.y, rb0.z, rb0.w, rb1.x, rb1.y, rb1.z, rb1.w};
#pragma unroll
            for (int i = 0; i < 8; i++)
#pragma unroll
                for (int j = 0; j < 8; j++)
                    acc[i][j] = fmaf(ra[i], rb[j], acc[i][j]);
        }
        __syncthreads();
    }

    float bcache[8];
#pragma unroll
    for (int j = 0; j < 8; j++) bcache[j] = bias[bn * 128 + tc * 8 + j];

    float* Cb = C + (size_t)(bm * 128 + tr * 8) * N + bn * 128 + tc * 8;
#pragma unroll
    for (int i = 0; i < 8; i++) {
        float out[8];
#pragma unroll
        for (int j = 0; j < 8; j++) {
            float v = acc[i][j] + bcache[j];
            if (MODE == 1) v = silu_f(v);
            else if (MODE == 2) v = softplus_f(v);
            out[j] = v;
        }
        *(float4*)(Cb + (size_t)i * N)     = *(float4*)&out[0];
        *(float4*)(Cb + (size_t)i * N + 4) = *(float4*)&out[4];
    }
}

// ---------------- depthwise conv3 (same pad over T) + silu ----------------
__global__ __launch_bounds__(256)
void conv_silu_kernel(const float* __restrict__ x1, const float* __restrict__ w,
                      const float* __restrict__ cb, float* __restrict__ x3)
{
    const int total = BB * TT * DD;
    for (int idx = blockIdx.x * blockDim.x + threadIdx.x; idx < total;
         idx += gridDim.x * blockDim.x) {
        int d = idx & (DD - 1);
        int t = (idx / DD) & (TT - 1);
        float c = x1[idx] * w[d * 3 + 1] + cb[d];
        if (t > 0)      c = fmaf(x1[idx - DD], w[d * 3 + 0], c);
        if (t < TT - 1) c = fmaf(x1[idx + DD], w[d * 3 + 2], c);
        x3[idx] = silu_f(c);
    }
}

// ---------------- B/C projections: [4096,1024] @ [1024,16] x2 ----------------
__global__ __launch_bounds__(256)
void proj_bc_kernel(const float* __restrict__ X,
                    const float* __restrict__ Wb, const float* __restrict__ Wc,
                    const float* __restrict__ bb, const float* __restrict__ bc,
                    float* __restrict__ Bm, float* __restrict__ Cm)
{
    __shared__ float Xs[32][33];
    __shared__ float Ws[32][32];   // [k][c] : c<16 -> Wb, else Wc

    const int tid = threadIdx.x;
    const int row0 = blockIdx.x * 32;
    const int c = tid & 31;
    const int rq = tid >> 5;       // 0..7, each handles 4 rows

    float acc[4] = {0.f, 0.f, 0.f, 0.f};

    const int lr = tid / 8;              // 0..31
    const int lc = (tid % 8) * 4;        // 0..28

    for (int k0 = 0; k0 < DD; k0 += 32) {
        float4 xv = *(const float4*)(X + (size_t)(row0 + lr) * DD + k0 + lc);
        Xs[lr][lc + 0] = xv.x; Xs[lr][lc + 1] = xv.y;
        Xs[lr][lc + 2] = xv.z; Xs[lr][lc + 3] = xv.w;
#pragma unroll
        for (int q = 0; q < 4; q++) {
            int cc = lc + q;
            float wv = (cc < 16) ? Wb[(size_t)(k0 + lr) * 16 + cc]
                                 : Wc[(size_t)(k0 + lr) * 16 + cc - 16];
            Ws[lr][cc] = wv;
        }
        __syncthreads();
#pragma unroll
        for (int kk = 0; kk < 32; kk++) {
            float w = Ws[kk][c];
#pragma unroll
            for (int r = 0; r < 4; r++)
                acc[r] = fmaf(Xs[rq * 4 + r][kk], w, acc[r]);
        }
        __syncthreads();
    }

#pragma unroll
    for (int r = 0; r < 4; r++) {
        int row = row0 + rq * 4 + r;
        if (c < 16) Bm[(size_t)row * 16 + c]      = acc[r] + bb[c];
        else        Cm[(size_t)row * 16 + c - 16] = acc[r] + bc[c - 16];
    }
}

// ---------------- selective scan ----------------
// block = 128 threads = 8 d-lanes x 16 n-lanes; grid = B * D/8 = 512
// h[b,d,n] kept in a register; y = sum_n h*C via shfl_xor over 16 lanes.
#define SCHUNK 32
__global__ __launch_bounds__(128)
void scan_kernel(const float* __restrict__ dt, const float* __restrict__ x,
                 const float* __restrict__ Bm, const float* __restrict__ Cm,
                 const float* __restrict__ A,  const float* __restrict__ z,
                 float* __restrict__ g)
{
    const int blk = blockIdx.x;
    const int b = blk >> 7;            // D/8 = 128 blocks per batch
    const int d0 = (blk & 127) * 8;
    const int tid = threadIdx.x;
    const int n = tid & 15;
    const int dl = tid >> 4;           // 0..7
    const int d = d0 + dl;

    const float a = A[(size_t)d * NN + n];
    float h = 0.f;

    __shared__ float s_dt[SCHUNK][8], s_x[SCHUNK][8], s_z[SCHUNK][8];
    __shared__ float s_B[SCHUNK][16], s_C[SCHUNK][16];
    __shared__ float s_y[SCHUNK][8];

    const size_t base = (size_t)b * TT * DD;
    const int li = tid / 4;            // 0..31
    const int lj2 = (tid % 4) * 2;     // 0,2,4,6
    const int lj4 = (tid % 4) * 4;     // 0,4,8,12

    for (int t0 = 0; t0 < TT; t0 += SCHUNK) {
        // stage inputs (coalesced-ish, vectorized)
        size_t rbase = base + (size_t)(t0 + li) * DD + d0;
        *(float2*)&s_dt[li][lj2] = *(const float2*)(dt + rbase + lj2);
        *(float2*)&s_x [li][lj2] = *(const float2*)(x  + rbase + lj2);
        *(float2*)&s_z [li][lj2] = *(const float2*)(z  + rbase + lj2);
        size_t nbase = ((size_t)b * TT + t0 + li) * NN;
        *(float4*)&s_B[li][lj4] = *(const float4*)(Bm + nbase + lj4);
        *(float4*)&s_C[li][lj4] = *(const float4*)(Cm + nbase + lj4);
        __syncthreads();

#pragma unroll 8
        for (int i = 0; i < SCHUNK; i++) {
            float dtv = s_dt[i][dl];
            float xv  = s_x[i][dl];
            float Bv  = s_B[i][n];
            float Cv  = s_C[i][n];
            float da  = __expf(dtv * a);
            h = fmaf(da, h, dtv * Bv * xv);
            float p = h * Cv;
            p += __shfl_xor_sync(0xffffffffu, p, 1);
            p += __shfl_xor_sync(0xffffffffu, p, 2);
            p += __shfl_xor_sync(0xffffffffu, p, 4);
            p += __shfl_xor_sync(0xffffffffu, p, 8);
            if (n == 0) s_y[i][dl] = p * s_z[i][dl];
        }
        __syncthreads();

        *(float2*)(g + rbase + lj2) = *(float2*)&s_y[li][lj2];
        // next chunk's staging is guarded by the sync after it; s_y reads here
        // are ordered vs next chunk's s_y writes by the sync after staging.
        __syncthreads();
    }
}

// ---------------- launch ----------------
extern "C" void kernel_launch(void* const* d_in, const int* in_sizes, int n_in,
                              void* d_out, int out_size)
{
    const float* u    = (const float*)d_in[0];
    const float* Win  = (const float*)d_in[1];
    const float* b_in = (const float*)d_in[2];
    const float* Wg   = (const float*)d_in[3];
    const float* bg   = (const float*)d_in[4];
    const float* Wout = (const float*)d_in[5];
    const float* bout = (const float*)d_in[6];
    const float* convw= (const float*)d_in[7];
    const float* convb= (const float*)d_in[8];
    const float* A    = (const float*)d_in[9];
    const float* Wb   = (const float*)d_in[10];
    const float* bb   = (const float*)d_in[11];
    const float* Wc   = (const float*)d_in[12];
    const float* bc   = (const float*)d_in[13];
    const float* Wdt  = (const float*)d_in[14];
    const float* bdt  = (const float*)d_in[15];
    float* out = (float*)d_out;

    float *x1, *zb, *x3, *dtb, *Bmb, *Cmb, *yb;
    cudaGetSymbolAddress((void**)&x1,  g_x1);
    cudaGetSymbolAddress((void**)&zb,  g_z);
    cudaGetSymbolAddress((void**)&x3,  g_x3);
    cudaGetSymbolAddress((void**)&dtb, g_dt);
    cudaGetSymbolAddress((void**)&Bmb, g_Bm);
    cudaGetSymbolAddress((void**)&Cmb, g_Cm);
    cudaGetSymbolAddress((void**)&yb,  g_y);

    dim3 gg(DD / 128, MM / 128);   // (8, 32)

    sgemm128<0><<<gg, 256>>>(u, Win, b_in, x1, MM, DD, DD);
    sgemm128<1><<<gg, 256>>>(u, Wg,  bg,   zb, MM, DD, DD);
    conv_silu_kernel<<<2048, 256>>>(x1, convw, convb, x3);
    sgemm128<2><<<gg, 256>>>(x3, Wdt, bdt, dtb, MM, DD, DD);
    proj_bc_kernel<<<MM / 32, 256>>>(x3, Wb, Wc, bb, bc, Bmb, Cmb);
    scan_kernel<<<BB * (DD / 8), 128>>>(dtb, x3, Bmb, Cmb, A, zb, yb);
    sgemm128<0><<<gg, 256>>>(yb, Wout, bout, out, MM, DD, DD);
}

// round 3
// speedup vs baseline: 1.7929x; 1.7929x over previous
#include <cuda_runtime.h>
#include <cuda_bf16.h>
#include <math.h>
#include <stdint.h>

#define BB 4
#define TT 1024
#define DD 1024
#define NN 16
#define MM (BB*TT)   // 4096

// GEMM tiling (mma.sync path)
#define Bb16 __nv_bfloat16
#define GBM 128
#define GBN 128
#define GBK 32
#define ROWB 80                 // padded row bytes: 32*2 + 16
#define TILE_B (128*ROWB)       // 10240
#define OFF_AH 0
#define OFF_AL (TILE_B)
#define OFF_BH (2*TILE_B)
#define OFF_BL (3*TILE_B)
#define STAGE_B (4*TILE_B)      // 40960
#define GEMM_SMEM (2*STAGE_B)   // 81920
#define NSTAGE (DD/GBK)         // 32

// ---------------- scratch (no allocations allowed) ----------------
__device__ __align__(256) float g_x1[MM*DD];
__device__ __align__(256) float g_z [MM*DD];
__device__ __align__(256) float g_x3[MM*DD];
__device__ __align__(256) float g_dt[MM*DD];
__device__ __align__(256) float g_Bm[MM*NN];
__device__ __align__(256) float g_Cm[MM*NN];

__device__ __align__(256) Bb16 g_uh[MM*DD],  g_ul[MM*DD];
__device__ __align__(256) Bb16 g_x3h[MM*DD], g_x3l[MM*DD];
__device__ __align__(256) Bb16 g_yh[MM*DD],  g_yl[MM*DD];
__device__ __align__(256) Bb16 g_Wint_h[DD*DD], g_Wint_l[DD*DD];
__device__ __align__(256) Bb16 g_Wgt_h [DD*DD], g_Wgt_l [DD*DD];
__device__ __align__(256) Bb16 g_Wdtt_h[DD*DD], g_Wdtt_l[DD*DD];
__device__ __align__(256) Bb16 g_Wot_h [DD*DD], g_Wot_l [DD*DD];

__device__ __forceinline__ float silu_f(float v) { return v / (1.f + __expf(-v)); }
__device__ __forceinline__ float softplus_f(float v) { return (v > 20.f) ? v : log1pf(__expf(v)); }

__device__ __forceinline__ uint32_t smem_to_u32(const void* p) {
    uint32_t a;
    asm("{ .reg .u64 t; cvta.to.shared.u64 t, %1; cvt.u32.u64 %0, t; }" : "=r"(a) : "l"(p));
    return a;
}
__device__ __forceinline__ void cpa16(uint32_t s, const void* g) {
    asm volatile("cp.async.cg.shared.global [%0], [%1], 16;\n" :: "r"(s), "l"(g));
}
__device__ __forceinline__ void cp_commit() { asm volatile("cp.async.commit_group;\n" ::: "memory"); }
template<int N> __device__ __forceinline__ void cp_wait() { asm volatile("cp.async.wait_group %0;\n" :: "n"(N) : "memory"); }

__device__ __forceinline__ void ldsm_x4(uint32_t* r, uint32_t addr) {
    asm volatile("ldmatrix.sync.aligned.m8n8.x4.shared.b16 {%0,%1,%2,%3}, [%4];"
        : "=r"(r[0]), "=r"(r[1]), "=r"(r[2]), "=r"(r[3]) : "r"(addr));
}
__device__ __forceinline__ void ldsm_x2(uint32_t* r, uint32_t addr) {
    asm volatile("ldmatrix.sync.aligned.m8n8.x2.shared.b16 {%0,%1}, [%2];"
        : "=r"(r[0]), "=r"(r[1]) : "r"(addr));
}
__device__ __forceinline__ void mma16816(float* c, const uint32_t* a, const uint32_t* b) {
    asm volatile("mma.sync.aligned.m16n8k16.row.col.f32.bf16.bf16.f32 "
        "{%0,%1,%2,%3}, {%4,%5,%6,%7}, {%8,%9}, {%0,%1,%2,%3};"
        : "+f"(c[0]), "+f"(c[1]), "+f"(c[2]), "+f"(c[3])
        : "r"(a[0]), "r"(a[1]), "r"(a[2]), "r"(a[3]), "r"(b[0]), "r"(b[1]));
}

__device__ __forceinline__ void split2(float v, Bb16& h, Bb16& l) {
    h = __float2bfloat16(v);
    l = __float2bfloat16(v - __bfloat162float(h));
}

// ---------------- 3x-bf16 GEMM via mma.sync ----------------
// C[4096,1024] = A @ W (+bias, act). A as (Ah,Al) [M,K] row-major bf16,
// W as (Bh,Bl) [N,K] row-major bf16 (pre-transposed). MODE 0:none 1:silu 2:softplus
template<int MODE>
__global__ __launch_bounds__(256, 2)
void gemm_mma(const Bb16* __restrict__ Ah, const Bb16* __restrict__ Al,
              const Bb16* __restrict__ Bh, const Bb16* __restrict__ Bl,
              const float* __restrict__ bias, float* __restrict__ C)
{
    extern __shared__ char smem[];
    const uint32_t sb = smem_to_u32(smem);
    const int tid = threadIdx.x;
    const int lane = tid & 31;
    const int wid = tid >> 5;
    const int wm = wid & 1;          // 2 warps in M
    const int wn = wid >> 1;         // 4 warps in N
    const int bn = blockIdx.x, bm = blockIdx.y;

    float acc[4][4][4];
#pragma unroll
    for (int i = 0; i < 4; i++)
#pragma unroll
        for (int j = 0; j < 4; j++)
#pragma unroll
            for (int k = 0; k < 4; k++) acc[i][j][k] = 0.f;

    const int lrow = tid >> 1;            // 0..127
    const int lc0  = (tid & 1) * 2;       // chunk base 0 / 2

    const Bb16* gAh = Ah + (size_t)(bm * GBM + lrow) * DD + lc0 * 8;
    const Bb16* gAl = Al + (size_t)(bm * GBM + lrow) * DD + lc0 * 8;
    const Bb16* gBh = Bh + (size_t)(bn * GBN + lrow) * DD + lc0 * 8;
    const Bb16* gBl = Bl + (size_t)(bn * GBN + lrow) * DD + lc0 * 8;
    const uint32_t srow = (uint32_t)lrow * ROWB + (uint32_t)lc0 * 16;

    auto load_stage = [&](int buf, int s) {
        const uint32_t st = sb + (uint32_t)buf * STAGE_B;
        const size_t k0 = (size_t)s * GBK;
        cpa16(st + OFF_AH + srow,      gAh + k0);
        cpa16(st + OFF_AH + srow + 16, gAh + k0 + 8);
        cpa16(st + OFF_AL + srow,      gAl + k0);
        cpa16(st + OFF_AL + srow + 16, gAl + k0 + 8);
        cpa16(st + OFF_BH + srow,      gBh + k0);
        cpa16(st + OFF_BH + srow + 16, gBh + k0 + 8);
        cpa16(st + OFF_BL + srow,      gBl + k0);
        cpa16(st + OFF_BL + srow + 16, gBl + k0 + 8);
        cp_commit();
    };

    load_stage(0, 0);
    load_stage(1, 1);

    // ldmatrix per-lane address components
    const uint32_t a_off = (uint32_t)(wm * 64 + (lane & 15)) * ROWB + ((lane >> 4) * 16);
    const uint32_t b_off = (uint32_t)(wn * 32 + (lane & 7)) * ROWB + (((lane >> 3) & 1) * 16);

    for (int s = 0; s < NSTAGE; s++) {
        const int buf = s & 1;
        if (s < NSTAGE - 1) cp_wait<1>(); else cp_wait<0>();
        __syncthreads();

        const uint32_t st = sb + (uint32_t)buf * STAGE_B;
#pragma unroll
        for (int k16 = 0; k16 < 2; k16++) {
            const uint32_t kb = (uint32_t)k16 * 32;
            uint32_t bhf[4][2], blf[4][2];
#pragma unroll
            for (int nt = 0; nt < 4; nt++) {
                uint32_t ad = st + OFF_BH + b_off + (uint32_t)nt * (8 * ROWB) + kb;
                ldsm_x2(bhf[nt], ad);
                ldsm_x2(blf[nt], ad + (OFF_BL - OFF_BH));
            }
#pragma unroll
            for (int mt = 0; mt < 4; mt++) {
                uint32_t ad = st + OFF_AH + a_off + (uint32_t)mt * (16 * ROWB) + kb;
                uint32_t ahf[4], alf[4];
                ldsm_x4(ahf, ad);
                ldsm_x4(alf, ad + (OFF_AL - OFF_AH));
#pragma unroll
                for (int nt = 0; nt < 4; nt++) {
                    mma16816(acc[mt][nt], ahf, bhf[nt]);
                    mma16816(acc[mt][nt], ahf, blf[nt]);
                    mma16816(acc[mt][nt], alf, bhf[nt]);
                }
            }
        }
        __syncthreads();
        if (s + 2 < NSTAGE) load_stage(buf, s + 2);
    }

    // epilogue
    const int row0 = bm * GBM + wm * 64 + (lane >> 2);
    const int col0 = bn * GBN + wn * 32 + (lane & 3) * 2;
#pragma unroll
    for (int mt = 0; mt < 4; mt++) {
#pragma unroll
        for (int nt = 0; nt < 4; nt++) {
            const int col = col0 + nt * 8;
            float b0 = bias[col], b1 = bias[col + 1];
#pragma unroll
            for (int half = 0; half < 2; half++) {
                const int row = row0 + mt * 16 + half * 8;
                float v0 = acc[mt][nt][half * 2 + 0] + b0;
                float v1 = acc[mt][nt][half * 2 + 1] + b1;
                if (MODE == 1) { v0 = silu_f(v0); v1 = silu_f(v1); }
                else if (MODE == 2) { v0 = softplus_f(v0); v1 = softplus_f(v1); }
                float2 w; w.x = v0; w.y = v1;
                *(float2*)(C + (size_t)row * DD + col) = w;
            }
        }
    }
}

// ---------------- elementwise split: fp32 -> bf16 hi/lo ----------------
__global__ __launch_bounds__(256)
void split_kernel(const float* __restrict__ X, Bb16* __restrict__ H,
                  Bb16* __restrict__ L, int n4)
{
    for (int i = blockIdx.x * blockDim.x + threadIdx.x; i < n4; i += gridDim.x * blockDim.x) {
        float4 v = ((const float4*)X)[i];
        Bb16 h0, l0, h1, l1, h2, l2, h3, l3;
        split2(v.x, h0, l0); split2(v.y, h1, l1); split2(v.z, h2, l2); split2(v.w, h3, l3);
        __nv_bfloat162 hh0; hh0.x = h0; hh0.y = h1;
        __nv_bfloat162 hh1; hh1.x = h2; hh1.y = h3;
        __nv_bfloat162 ll0; ll0.x = l0; ll0.y = l1;
        __nv_bfloat162 ll1; ll1.x = l2; ll1.y = l3;
        ((__nv_bfloat162*)H)[i * 2]     = hh0;
        ((__nv_bfloat162*)H)[i * 2 + 1] = hh1;
        ((__nv_bfloat162*)L)[i * 2]     = ll0;
        ((__nv_bfloat162*)L)[i * 2 + 1] = ll1;
    }
}

// ---------------- transpose + split: W[K,N] fp32 -> Wt[N,K] bf16 hi/lo ----------------
__global__ __launch_bounds__(256)
void tsplit_kernel(const float* __restrict__ W, Bb16* __restrict__ Th, Bb16* __restrict__ Tl)
{
    __shared__ float s[32][33];
    const int bx = blockIdx.x * 32, by = blockIdx.y * 32;
    const int tx = threadIdx.x, ty = threadIdx.y;  // block (32,8)
#pragma unroll
    for (int j = ty; j < 32; j += 8)
        s[j][tx] = W[(size_t)(by + j) * DD + bx + tx];
    __syncthreads();
#pragma unroll
    for (int j = ty; j < 32; j += 8) {
        float v = s[tx][j];
        Bb16 h, l;
        split2(v, h, l);
        Th[(size_t)(bx + j) * DD + by + tx] = h;
        Tl[(size_t)(bx + j) * DD + by + tx] = l;
    }
}

// ---------------- depthwise conv3 + silu (+ bf16 split out) ----------------
__global__ __launch_bounds__(256)
void conv_silu_kernel(const float* __restrict__ x1, const float* __restrict__ w,
                      const float* __restrict__ cb, float* __restrict__ x3,
                      Bb16* __restrict__ x3h, Bb16* __restrict__ x3l)
{
    const int total2 = BB * TT * DD / 2;
    for (int i2 = blockIdx.x * blockDim.x + threadIdx.x; i2 < total2; i2 += gridDim.x * blockDim.x) {
        int idx = i2 * 2;
        int d = idx & (DD - 1);
        int t = (idx / DD) & (TT - 1);
        float2 xc = *(const float2*)(x1 + idx);
        float c0 = xc.x * w[d * 3 + 1] + cb[d];
        float c1 = xc.y * w[(d + 1) * 3 + 1] + cb[d + 1];
        if (t > 0) {
            float2 xm = *(const float2*)(x1 + idx - DD);
            c0 = fmaf(xm.x, w[d * 3], c0);
            c1 = fmaf(xm.y, w[(d + 1) * 3], c1);
        }
        if (t < TT - 1) {
            float2 xp = *(const float2*)(x1 + idx + DD);
            c0 = fmaf(xp.x, w[d * 3 + 2], c0);
            c1 = fmaf(xp.y, w[(d + 1) * 3 + 2], c1);
        }
        float2 r; r.x = silu_f(c0); r.y = silu_f(c1);
        *(float2*)(x3 + idx) = r;
        Bb16 h0, l0, h1, l1;
        split2(r.x, h0, l0); split2(r.y, h1, l1);
        __nv_bfloat162 hh; hh.x = h0; hh.y = h1;
        __nv_bfloat162 ll; ll.x = l0; ll.y = l1;
        *(__nv_bfloat162*)(x3h + idx) = hh;
        *(__nv_bfloat162*)(x3l + idx) = ll;
    }
}

// ---------------- B/C projections ----------------
__global__ __launch_bounds__(256)
void proj_bc_kernel(const float* __restrict__ X,
                    const float* __restrict__ Wb, const float* __restrict__ Wc,
                    const float* __restrict__ bb, const float* __restrict__ bc,
                    float* __restrict__ Bm, float* __restrict__ Cm)
{
    __shared__ float Xs[32][33];
    __shared__ float Ws[32][32];
    const int tid = threadIdx.x;
    const int row0 = blockIdx.x * 32;
    const int c = tid & 31;
    const int rq = tid >> 5;
    float acc[4] = {0.f, 0.f, 0.f, 0.f};
    const int lr = tid / 8;
    const int lc = (tid % 8) * 4;

    for (int k0 = 0; k0 < DD; k0 += 32) {
        float4 xv = *(const float4*)(X + (size_t)(row0 + lr) * DD + k0 + lc);
        Xs[lr][lc + 0] = xv.x; Xs[lr][lc + 1] = xv.y;
        Xs[lr][lc + 2] = xv.z; Xs[lr][lc + 3] = xv.w;
#pragma unroll
        for (int q = 0; q < 4; q++) {
            int cc = lc + q;
            float wv = (cc < 16) ? Wb[(size_t)(k0 + lr) * 16 + cc]
                                 : Wc[(size_t)(k0 + lr) * 16 + cc - 16];
            Ws[lr][cc] = wv;
        }
        __syncthreads();
#pragma unroll
        for (int kk = 0; kk < 32; kk++) {
            float w = Ws[kk][c];
#pragma unroll
            for (int r = 0; r < 4; r++)
                acc[r] = fmaf(Xs[rq * 4 + r][kk], w, acc[r]);
        }
        __syncthreads();
    }
#pragma unroll
    for (int r = 0; r < 4; r++) {
        int row = row0 + rq * 4 + r;
        if (c < 16) Bm[(size_t)row * 16 + c]      = acc[r] + bb[c];
        else        Cm[(size_t)row * 16 + c - 16] = acc[r] + bc[c - 16];
    }
}

// ---------------- selective scan (outputs bf16 hi/lo of y*z) ----------------
#define SCHUNK 32
__global__ __launch_bounds__(128)
void scan_kernel(const float* __restrict__ dt, const float* __restrict__ x,
                 const float* __restrict__ Bm, const float* __restrict__ Cm,
                 const float* __restrict__ A,  const float* __restrict__ z,
                 Bb16* __restrict__ yh, Bb16* __restrict__ yl)
{
    const int blk = blockIdx.x;
    const int b = blk >> 7;
    const int d0 = (blk & 127) * 8;
    const int tid = threadIdx.x;
    const int n = tid & 15;
    const int dl = tid >> 4;
    const int d = d0 + dl;

    const float a = A[(size_t)d * NN + n];
    float h = 0.f;

    __shared__ float s_dt[SCHUNK][8], s_x[SCHUNK][8], s_z[SCHUNK][8];
    __shared__ float s_B[SCHUNK][16], s_C[SCHUNK][16];
    __shared__ float s_y[SCHUNK][8];

    const size_t base = (size_t)b * TT * DD;
    const int li = tid / 4;
    const int lj2 = (tid % 4) * 2;
    const int lj4 = (tid % 4) * 4;

    for (int t0 = 0; t0 < TT; t0 += SCHUNK) {
        size_t rbase = base + (size_t)(t0 + li) * DD + d0;
        *(float2*)&s_dt[li][lj2] = *(const float2*)(dt + rbase + lj2);
        *(float2*)&s_x [li][lj2] = *(const float2*)(x  + rbase + lj2);
        *(float2*)&s_z [li][lj2] = *(const float2*)(z  + rbase + lj2);
        size_t nbase = ((size_t)b * TT + t0 + li) * NN;
        *(float4*)&s_B[li][lj4] = *(const float4*)(Bm + nbase + lj4);
        *(float4*)&s_C[li][lj4] = *(const float4*)(Cm + nbase + lj4);
        __syncthreads();

#pragma unroll 8
        for (int i = 0; i < SCHUNK; i++) {
            float dtv = s_dt[i][dl];
            float xv  = s_x[i][dl];
            float Bv  = s_B[i][n];
            float Cv  = s_C[i][n];
            float da  = __expf(dtv * a);
            h = fmaf(da, h, dtv * Bv * xv);
            float p = h * Cv;
            p += __shfl_xor_sync(0xffffffffu, p, 1);
            p += __shfl_xor_sync(0xffffffffu, p, 2);
            p += __shfl_xor_sync(0xffffffffu, p, 4);
            p += __shfl_xor_sync(0xffffffffu, p, 8);
            if (n == 0) s_y[i][dl] = p * s_z[i][dl];
        }
        __syncthreads();

        float2 v = *(float2*)&s_y[li][lj2];
        Bb16 h0, l0, h1, l1;
        split2(v.x, h0, l0); split2(v.y, h1, l1);
        __nv_bfloat162 hh; hh.x = h0; hh.y = h1;
        __nv_bfloat162 ll; ll.x = l0; ll.y = l1;
        *(__nv_bfloat162*)(yh + rbase + lj2) = hh;
        *(__nv_bfloat162*)(yl + rbase + lj2) = ll;
        __syncthreads();
    }
}

// ---------------- launch ----------------
extern "C" void kernel_launch(void* const* d_in, const int* in_sizes, int n_in,
                              void* d_out, int out_size)
{
    const float* u    = (const float*)d_in[0];
    const float* Win  = (const float*)d_in[1];
    const float* b_in = (const float*)d_in[2];
    const float* Wg   = (const float*)d_in[3];
    const float* bg   = (const float*)d_in[4];
    const float* Wout = (const float*)d_in[5];
    const float* bout = (const float*)d_in[6];
    const float* convw= (const float*)d_in[7];
    const float* convb= (const float*)d_in[8];
    const float* A    = (const float*)d_in[9];
    const float* Wb   = (const float*)d_in[10];
    const float* bb   = (const float*)d_in[11];
    const float* Wc   = (const float*)d_in[12];
    const float* bc   = (const float*)d_in[13];
    const float* Wdt  = (const float*)d_in[14];
    const float* bdt  = (const float*)d_in[15];
    float* out = (float*)d_out;

    float *x1, *zb, *x3, *dtb, *Bmb, *Cmb;
    cudaGetSymbolAddress((void**)&x1,  g_x1);
    cudaGetSymbolAddress((void**)&zb,  g_z);
    cudaGetSymbolAddress((void**)&x3,  g_x3);
    cudaGetSymbolAddress((void**)&dtb, g_dt);
    cudaGetSymbolAddress((void**)&Bmb, g_Bm);
    cudaGetSymbolAddress((void**)&Cmb, g_Cm);

    Bb16 *uh, *ul, *x3h, *x3l, *yh, *yl;
    Bb16 *Wint_h, *Wint_l, *Wgt_h, *Wgt_l, *Wdtt_h, *Wdtt_l, *Wot_h, *Wot_l;
    cudaGetSymbolAddress((void**)&uh,  g_uh);   cudaGetSymbolAddress((void**)&ul,  g_ul);
    cudaGetSymbolAddress((void**)&x3h, g_x3h);  cudaGetSymbolAddress((void**)&x3l, g_x3l);
    cudaGetSymbolAddress((void**)&yh,  g_yh);   cudaGetSymbolAddress((void**)&yl,  g_yl);
    cudaGetSymbolAddress((void**)&Wint_h, g_Wint_h); cudaGetSymbolAddress((void**)&Wint_l, g_Wint_l);
    cudaGetSymbolAddress((void**)&Wgt_h,  g_Wgt_h);  cudaGetSymbolAddress((void**)&Wgt_l,  g_Wgt_l);
    cudaGetSymbolAddress((void**)&Wdtt_h, g_Wdtt_h); cudaGetSymbolAddress((void**)&Wdtt_l, g_Wdtt_l);
    cudaGetSymbolAddress((void**)&Wot_h,  g_Wot_h);  cudaGetSymbolAddress((void**)&Wot_l,  g_Wot_l);

    cudaFuncSetAttribute((const void*)gemm_mma<0>, cudaFuncAttributeMaxDynamicSharedMemorySize, GEMM_SMEM);
    cudaFuncSetAttribute((const void*)gemm_mma<1>, cudaFuncAttributeMaxDynamicSharedMemorySize, GEMM_SMEM);
    cudaFuncSetAttribute((const void*)gemm_mma<2>, cudaFuncAttributeMaxDynamicSharedMemorySize, GEMM_SMEM);

    dim3 tg(32, 32);
    dim3 tb(32, 8);
    tsplit_kernel<<<tg, tb>>>(Win,  Wint_h, Wint_l);
    tsplit_kernel<<<tg, tb>>>(Wg,   Wgt_h,  Wgt_l);
    tsplit_kernel<<<tg, tb>>>(Wdt,  Wdtt_h, Wdtt_l);
    tsplit_kernel<<<tg, tb>>>(Wout, Wot_h,  Wot_l);
    split_kernel<<<2048, 256>>>(u, uh, ul, MM * DD / 4);

    dim3 gg(DD / GBN, MM / GBM);  // (8, 32)
    gemm_mma<0><<<gg, 256, GEMM_SMEM>>>(uh, ul, Wint_h, Wint_l, b_in, x1);
    gemm_mma<1><<<gg, 256, GEMM_SMEM>>>(uh, ul, Wgt_h,  Wgt_l,  bg,   zb);
    conv_silu_kernel<<<2048, 256>>>(x1, convw, convb, x3, x3h, x3l);
    gemm_mma<2><<<gg, 256, GEMM_SMEM>>>(x3h, x3l, Wdtt_h, Wdtt_l, bdt, dtb);
    proj_bc_kernel<<<MM / 32, 256>>>(x3, Wb, Wc, bb, bc, Bmb, Cmb);
    scan_kernel<<<BB * (DD / 8), 128>>>(dtb, x3, Bmb, Cmb, A, zb, yh, yl);
    gemm_mma<0><<<gg, 256, GEMM_SMEM>>>(yh, yl, Wot_h, Wot_l, bout, out);
}

// round 4
// speedup vs baseline: 1.9241x; 1.0732x over previous
#include <cuda_runtime.h>
#include <cuda_bf16.h>
#include <math.h>
#include <stdint.h>

#define BB 4
#define TT 1024
#define DD 1024
#define NN 16
#define MM (BB*TT)   // 4096

// GEMM tiling (mma.sync path)
#define Bb16 __nv_bfloat16
#define GBM 128
#define GBN 128
#define GBK 16
#define ROWB 48                 // padded row bytes: 16*2 + 16 (conflict-free: 48B stride)
#define TILE_B (128*ROWB)       // 6144
#define OFF_AH 0
#define OFF_AL (TILE_B)
#define OFF_BH (2*TILE_B)
#define OFF_BL (3*TILE_B)
#define STAGE_B (4*TILE_B)      // 24576
#define NPIPE 4
#define GEMM_SMEM (NPIPE*STAGE_B)   // 98304
#define NSTAGE (DD/GBK)         // 64

// ---------------- scratch (no allocations allowed) ----------------
__device__ __align__(256) float g_x1[MM*DD];
__device__ __align__(256) float g_z [MM*DD];
__device__ __align__(256) float g_x3[MM*DD];
__device__ __align__(256) float g_dt[MM*DD];
__device__ __align__(256) float g_Bm[MM*NN];
__device__ __align__(256) float g_Cm[MM*NN];

__device__ __align__(256) Bb16 g_uh[MM*DD],  g_ul[MM*DD];
__device__ __align__(256) Bb16 g_x3h[MM*DD], g_x3l[MM*DD];
__device__ __align__(256) Bb16 g_yh[MM*DD],  g_yl[MM*DD];
__device__ __align__(256) Bb16 g_Wint_h[DD*DD], g_Wint_l[DD*DD];
__device__ __align__(256) Bb16 g_Wgt_h [DD*DD], g_Wgt_l [DD*DD];
__device__ __align__(256) Bb16 g_Wdtt_h[DD*DD], g_Wdtt_l[DD*DD];
__device__ __align__(256) Bb16 g_Wot_h [DD*DD], g_Wot_l [DD*DD];

__device__ __forceinline__ float silu_f(float v) { return v / (1.f + __expf(-v)); }
__device__ __forceinline__ float softplus_f(float v) { return (v > 20.f) ? v : log1pf(__expf(v)); }

__device__ __forceinline__ uint32_t smem_to_u32(const void* p) {
    uint32_t a;
    asm("{ .reg .u64 t; cvta.to.shared.u64 t, %1; cvt.u32.u64 %0, t; }" : "=r"(a) : "l"(p));
    return a;
}
__device__ __forceinline__ void cpa16(uint32_t s, const void* g) {
    asm volatile("cp.async.cg.shared.global [%0], [%1], 16;\n" :: "r"(s), "l"(g));
}
__device__ __forceinline__ void cp_commit() { asm volatile("cp.async.commit_group;\n" ::: "memory"); }
template<int N> __device__ __forceinline__ void cp_wait() { asm volatile("cp.async.wait_group %0;\n" :: "n"(N) : "memory"); }

__device__ __forceinline__ void ldsm_x4(uint32_t* r, uint32_t addr) {
    asm volatile("ldmatrix.sync.aligned.m8n8.x4.shared.b16 {%0,%1,%2,%3}, [%4];"
        : "=r"(r[0]), "=r"(r[1]), "=r"(r[2]), "=r"(r[3]) : "r"(addr));
}
__device__ __forceinline__ void ldsm_x2(uint32_t* r, uint32_t addr) {
    asm volatile("ldmatrix.sync.aligned.m8n8.x2.shared.b16 {%0,%1}, [%2];"
        : "=r"(r[0]), "=r"(r[1]) : "r"(addr));
}
__device__ __forceinline__ void mma16816(float* c, const uint32_t* a, const uint32_t* b) {
    asm volatile("mma.sync.aligned.m16n8k16.row.col.f32.bf16.bf16.f32 "
        "{%0,%1,%2,%3}, {%4,%5,%6,%7}, {%8,%9}, {%0,%1,%2,%3};"
        : "+f"(c[0]), "+f"(c[1]), "+f"(c[2]), "+f"(c[3])
        : "r"(a[0]), "r"(a[1]), "r"(a[2]), "r"(a[3]), "r"(b[0]), "r"(b[1]));
}

__device__ __forceinline__ void split2(float v, Bb16& h, Bb16& l) {
    h = __float2bfloat16(v);
    l = __float2bfloat16(v - __bfloat162float(h));
}

// ---------------- 3x-bf16 GEMM via mma.sync, 4-stage cp.async pipeline ----------------
// C[4096,1024] = A @ W (+bias, act). A as (Ah,Al) [M,K] row-major bf16,
// W as (Bh,Bl) [N,K] row-major bf16 (pre-transposed). MODE 0:none 1:silu 2:softplus
template<int MODE>
__global__ __launch_bounds__(256, 2)
void gemm_mma(const Bb16* __restrict__ Ah, const Bb16* __restrict__ Al,
              const Bb16* __restrict__ Bh, const Bb16* __restrict__ Bl,
              const float* __restrict__ bias, float* __restrict__ C)
{
    extern __shared__ char smem[];
    const uint32_t sb = smem_to_u32(smem);
    const int tid = threadIdx.x;
    const int lane = tid & 31;
    const int wid = tid >> 5;
    const int wm = wid & 1;          // 2 warps in M
    const int wn = wid >> 1;         // 4 warps in N
    const int bn = blockIdx.x, bm = blockIdx.y;

    float acc[4][4][4];
#pragma unroll
    for (int i = 0; i < 4; i++)
#pragma unroll
        for (int j = 0; j < 4; j++)
#pragma unroll
            for (int k = 0; k < 4; k++) acc[i][j][k] = 0.f;

    // loader: thread -> (row 0..127, 16B chunk 0..1), one cpa16 per tensor per stage
    const int lrow = tid >> 1;
    const int lch  = tid & 1;

    const Bb16* gAh = Ah + (size_t)(bm * GBM + lrow) * DD + lch * 8;
    const Bb16* gAl = Al + (size_t)(bm * GBM + lrow) * DD + lch * 8;
    const Bb16* gBh = Bh + (size_t)(bn * GBN + lrow) * DD + lch * 8;
    const Bb16* gBl = Bl + (size_t)(bn * GBN + lrow) * DD + lch * 8;
    const uint32_t srow = (uint32_t)lrow * ROWB + (uint32_t)lch * 16;

    auto load_stage = [&](int buf, int s) {
        const uint32_t st = sb + (uint32_t)buf * STAGE_B;
        const size_t k0 = (size_t)s * GBK;
        cpa16(st + OFF_AH + srow, gAh + k0);
        cpa16(st + OFF_AL + srow, gAl + k0);
        cpa16(st + OFF_BH + srow, gBh + k0);
        cpa16(st + OFF_BL + srow, gBl + k0);
        cp_commit();
    };

    load_stage(0, 0);
    load_stage(1, 1);
    load_stage(2, 2);

    // ldmatrix per-lane address components
    const uint32_t a_off = (uint32_t)(wm * 64 + (lane & 15)) * ROWB + ((lane >> 4) * 16);
    const uint32_t b_off = (uint32_t)(wn * 32 + (lane & 7)) * ROWB + (((lane >> 3) & 1) * 16);

    for (int s = 0; s < NSTAGE; s++) {
        const int buf = s & (NPIPE - 1);
        if (s < NSTAGE - 2)       cp_wait<2>();
        else if (s == NSTAGE - 2) cp_wait<1>();
        else                      cp_wait<0>();
        __syncthreads();

        const uint32_t st = sb + (uint32_t)buf * STAGE_B;
        uint32_t bhf[4][2], blf[4][2];
#pragma unroll
        for (int nt = 0; nt < 4; nt++) {
            uint32_t ad = st + OFF_BH + b_off + (uint32_t)nt * (8 * ROWB);
            ldsm_x2(bhf[nt], ad);
            ldsm_x2(blf[nt], ad + (OFF_BL - OFF_BH));
        }
#pragma unroll
        for (int mt = 0; mt < 4; mt++) {
            uint32_t ad = st + OFF_AH + a_off + (uint32_t)mt * (16 * ROWB);
            uint32_t ahf[4], alf[4];
            ldsm_x4(ahf, ad);
            ldsm_x4(alf, ad + (OFF_AL - OFF_AH));
#pragma unroll
            for (int nt = 0; nt < 4; nt++) {
                mma16816(acc[mt][nt], ahf, bhf[nt]);
                mma16816(acc[mt][nt], ahf, blf[nt]);
                mma16816(acc[mt][nt], alf, bhf[nt]);
            }
        }

        if (s + NPIPE - 1 < NSTAGE) load_stage((s + NPIPE - 1) & (NPIPE - 1), s + NPIPE - 1);
    }

    // epilogue
    const int row0 = bm * GBM + wm * 64 + (lane >> 2);
    const int col0 = bn * GBN + wn * 32 + (lane & 3) * 2;
#pragma unroll
    for (int mt = 0; mt < 4; mt++) {
#pragma unroll
        for (int nt = 0; nt < 4; nt++) {
            const int col = col0 + nt * 8;
            float b0 = bias[col], b1 = bias[col + 1];
#pragma unroll
            for (int half = 0; half < 2; half++) {
                const int row = row0 + mt * 16 + half * 8;
                float v0 = acc[mt][nt][half * 2 + 0] + b0;
                float v1 = acc[mt][nt][half * 2 + 1] + b1;
                if (MODE == 1) { v0 = silu_f(v0); v1 = silu_f(v1); }
                else if (MODE == 2) { v0 = softplus_f(v0); v1 = softplus_f(v1); }
                float2 w; w.x = v0; w.y = v1;
                *(float2*)(C + (size_t)row * DD + col) = w;
            }
        }
    }
}

// ---------------- elementwise split: fp32 -> bf16 hi/lo ----------------
__global__ __launch_bounds__(256)
void split_kernel(const float* __restrict__ X, Bb16* __restrict__ H,
                  Bb16* __restrict__ L, int n4)
{
    for (int i = blockIdx.x * blockDim.x + threadIdx.x; i < n4; i += gridDim.x * blockDim.x) {
        float4 v = ((const float4*)X)[i];
        Bb16 h0, l0, h1, l1, h2, l2, h3, l3;
        split2(v.x, h0, l0); split2(v.y, h1, l1); split2(v.z, h2, l2); split2(v.w, h3, l3);
        __nv_bfloat162 hh0; hh0.x = h0; hh0.y = h1;
        __nv_bfloat162 hh1; hh1.x = h2; hh1.y = h3;
        __nv_bfloat162 ll0; ll0.x = l0; ll0.y = l1;
        __nv_bfloat162 ll1; ll1.x = l2; ll1.y = l3;
        ((__nv_bfloat162*)H)[i * 2]     = hh0;
        ((__nv_bfloat162*)H)[i * 2 + 1] = hh1;
        ((__nv_bfloat162*)L)[i * 2]     = ll0;
        ((__nv_bfloat162*)L)[i * 2 + 1] = ll1;
    }
}

// ---------------- transpose + split: W[K,N] fp32 -> Wt[N,K] bf16 hi/lo ----------------
__global__ __launch_bounds__(256)
void tsplit_kernel(const float* __restrict__ W, Bb16* __restrict__ Th, Bb16* __restrict__ Tl)
{
    __shared__ float s[32][33];
    const int bx = blockIdx.x * 32, by = blockIdx.y * 32;
    const int tx = threadIdx.x, ty = threadIdx.y;  // block (32,8)
#pragma unroll
    for (int j = ty; j < 32; j += 8)
        s[j][tx] = W[(size_t)(by + j) * DD + bx + tx];
    __syncthreads();
#pragma unroll
    for (int j = ty; j < 32; j += 8) {
        float v = s[tx][j];
        Bb16 h, l;
        split2(v, h, l);
        Th[(size_t)(bx + j) * DD + by + tx] = h;
        Tl[(size_t)(bx + j) * DD + by + tx] = l;
    }
}

// ---------------- depthwise conv3 + silu (+ bf16 split out) ----------------
__global__ __launch_bounds__(256)
void conv_silu_kernel(const float* __restrict__ x1, const float* __restrict__ w,
                      const float* __restrict__ cb, float* __restrict__ x3,
                      Bb16* __restrict__ x3h, Bb16* __restrict__ x3l)
{
    const int total2 = BB * TT * DD / 2;
    for (int i2 = blockIdx.x * blockDim.x + threadIdx.x; i2 < total2; i2 += gridDim.x * blockDim.x) {
        int idx = i2 * 2;
        int d = idx & (DD - 1);
        int t = (idx / DD) & (TT - 1);
        float2 xc = *(const float2*)(x1 + idx);
        float c0 = xc.x * w[d * 3 + 1] + cb[d];
        float c1 = xc.y * w[(d + 1) * 3 + 1] + cb[d + 1];
        if (t > 0) {
            float2 xm = *(const float2*)(x1 + idx - DD);
            c0 = fmaf(xm.x, w[d * 3], c0);
            c1 = fmaf(xm.y, w[(d + 1) * 3], c1);
        }
        if (t < TT - 1) {
            float2 xp = *(const float2*)(x1 + idx + DD);
            c0 = fmaf(xp.x, w[d * 3 + 2], c0);
            c1 = fmaf(xp.y, w[(d + 1) * 3 + 2], c1);
        }
        float2 r; r.x = silu_f(c0); r.y = silu_f(c1);
        *(float2*)(x3 + idx) = r;
        Bb16 h0, l0, h1, l1;
        split2(r.x, h0, l0); split2(r.y, h1, l1);
        __nv_bfloat162 hh; hh.x = h0; hh.y = h1;
        __nv_bfloat162 ll; ll.x = l0; ll.y = l1;
        *(__nv_bfloat162*)(x3h + idx) = hh;
        *(__nv_bfloat162*)(x3l + idx) = ll;
    }
}

// ---------------- B/C projections ----------------
__global__ __launch_bounds__(256)
void proj_bc_kernel(const float* __restrict__ X,
                    const float* __restrict__ Wb, const float* __restrict__ Wc,
                    const float* __restrict__ bb, const float* __restrict__ bc,
                    float* __restrict__ Bm, float* __restrict__ Cm)
{
    __shared__ float Xs[32][33];
    __shared__ float Ws[32][32];
    const int tid = threadIdx.x;
    const int row0 = blockIdx.x * 32;
    const int c = tid & 31;
    const int rq = tid >> 5;
    float acc[4] = {0.f, 0.f, 0.f, 0.f};
    const int lr = tid / 8;
    const int lc = (tid % 8) * 4;

    for (int k0 = 0; k0 < DD; k0 += 32) {
        float4 xv = *(const float4*)(X + (size_t)(row0 + lr) * DD + k0 + lc);
        Xs[lr][lc + 0] = xv.x; Xs[lr][lc + 1] = xv.y;
        Xs[lr][lc + 2] = xv.z; Xs[lr][lc + 3] = xv.w;
#pragma unroll
        for (int q = 0; q < 4; q++) {
            int cc = lc + q;
            float wv = (cc < 16) ? Wb[(size_t)(k0 + lr) * 16 + cc]
                                 : Wc[(size_t)(k0 + lr) * 16 + cc - 16];
            Ws[lr][cc] = wv;
        }
        __syncthreads();
#pragma unroll
        for (int kk = 0; kk < 32; kk++) {
            float w = Ws[kk][c];
#pragma unroll
            for (int r = 0; r < 4; r++)
                acc[r] = fmaf(Xs[rq * 4 + r][kk], w, acc[r]);
        }
        __syncthreads();
    }
#pragma unroll
    for (int r = 0; r < 4; r++) {
        int row = row0 + rq * 4 + r;
        if (c < 16) Bm[(size_t)row * 16 + c]      = acc[r] + bb[c];
        else        Cm[(size_t)row * 16 + c - 16] = acc[r] + bc[c - 16];
    }
}

// ---------------- selective scan (outputs bf16 hi/lo of y*z) ----------------
#define SCHUNK 32
__global__ __launch_bounds__(128)
void scan_kernel(const float* __restrict__ dt, const float* __restrict__ x,
                 const float* __restrict__ Bm, const float* __restrict__ Cm,
                 const float* __restrict__ A,  const float* __restrict__ z,
                 Bb16* __restrict__ yh, Bb16* __restrict__ yl)
{
    const int blk = blockIdx.x;
    const int b = blk >> 7;
    const int d0 = (blk & 127) * 8;
    const int tid = threadIdx.x;
    const int n = tid & 15;
    const int dl = tid >> 4;
    const int d = d0 + dl;

    const float a = A[(size_t)d * NN + n];
    float h = 0.f;

    __shared__ float s_dt[SCHUNK][8], s_x[SCHUNK][8], s_z[SCHUNK][8];
    __shared__ float s_B[SCHUNK][16], s_C[SCHUNK][16];
    __shared__ float s_y[SCHUNK][8];

    const size_t base = (size_t)b * TT * DD;
    const int li = tid / 4;
    const int lj2 = (tid % 4) * 2;
    const int lj4 = (tid % 4) * 4;

    for (int t0 = 0; t0 < TT; t0 += SCHUNK) {
        size_t rbase = base + (size_t)(t0 + li) * DD + d0;
        *(float2*)&s_dt[li][lj2] = *(const float2*)(dt + rbase + lj2);
        *(float2*)&s_x [li][lj2] = *(const float2*)(x  + rbase + lj2);
        *(float2*)&s_z [li][lj2] = *(const float2*)(z  + rbase + lj2);
        size_t nbase = ((size_t)b * TT + t0 + li) * NN;
        *(float4*)&s_B[li][lj4] = *(const float4*)(Bm + nbase + lj4);
        *(float4*)&s_C[li][lj4] = *(const float4*)(Cm + nbase + lj4);
        __syncthreads();

#pragma unroll 8
        for (int i = 0; i < SCHUNK; i++) {
            float dtv = s_dt[i][dl];
            float xv  = s_x[i][dl];
            float Bv  = s_B[i][n];
            float Cv  = s_C[i][n];
            float da  = __expf(dtv * a);
            h = fmaf(da, h, dtv * Bv * xv);
            float p = h * Cv;
            p += __shfl_xor_sync(0xffffffffu, p, 1);
            p += __shfl_xor_sync(0xffffffffu, p, 2);
            p += __shfl_xor_sync(0xffffffffu, p, 4);
            p += __shfl_xor_sync(0xffffffffu, p, 8);
            if (n == 0) s_y[i][dl] = p * s_z[i][dl];
        }
        __syncthreads();

        float2 v = *(float2*)&s_y[li][lj2];
        Bb16 h0, l0, h1, l1;
        split2(v.x, h0, l0); split2(v.y, h1, l1);
        __nv_bfloat162 hh; hh.x = h0; hh.y = h1;
        __nv_bfloat162 ll; ll.x = l0; ll.y = l1;
        *(__nv_bfloat162*)(yh + rbase + lj2) = hh;
        *(__nv_bfloat162*)(yl + rbase + lj2) = ll;
        __syncthreads();
    }
}

// ---------------- launch ----------------
extern "C" void kernel_launch(void* const* d_in, const int* in_sizes, int n_in,
                              void* d_out, int out_size)
{
    const float* u    = (const float*)d_in[0];
    const float* Win  = (const float*)d_in[1];
    const float* b_in = (const float*)d_in[2];
    const float* Wg   = (const float*)d_in[3];
    const float* bg   = (const float*)d_in[4];
    const float* Wout = (const float*)d_in[5];
    const float* bout = (const float*)d_in[6];
    const float* convw= (const float*)d_in[7];
    const float* convb= (const float*)d_in[8];
    const float* A    = (const float*)d_in[9];
    const float* Wb   = (const float*)d_in[10];
    const float* bb   = (const float*)d_in[11];
    const float* Wc   = (const float*)d_in[12];
    const float* bc   = (const float*)d_in[13];
    const float* Wdt  = (const float*)d_in[14];
    const float* bdt  = (const float*)d_in[15];
    float* out = (float*)d_out;

    float *x1, *zb, *x3, *dtb, *Bmb, *Cmb;
    cudaGetSymbolAddress((void**)&x1,  g_x1);
    cudaGetSymbolAddress((void**)&zb,  g_z);
    cudaGetSymbolAddress((void**)&x3,  g_x3);
    cudaGetSymbolAddress((void**)&dtb, g_dt);
    cudaGetSymbolAddress((void**)&Bmb, g_Bm);
    cudaGetSymbolAddress((void**)&Cmb, g_Cm);

    Bb16 *uh, *ul, *x3h, *x3l, *yh, *yl;
    Bb16 *Wint_h, *Wint_l, *Wgt_h, *Wgt_l, *Wdtt_h, *Wdtt_l, *Wot_h, *Wot_l;
    cudaGetSymbolAddress((void**)&uh,  g_uh);   cudaGetSymbolAddress((void**)&ul,  g_ul);
    cudaGetSymbolAddress((void**)&x3h, g_x3h);  cudaGetSymbolAddress((void**)&x3l, g_x3l);
    cudaGetSymbolAddress((void**)&yh,  g_yh);   cudaGetSymbolAddress((void**)&yl,  g_yl);
    cudaGetSymbolAddress((void**)&Wint_h, g_Wint_h); cudaGetSymbolAddress((void**)&Wint_l, g_Wint_l);
    cudaGetSymbolAddress((void**)&Wgt_h,  g_Wgt_h);  cudaGetSymbolAddress((void**)&Wgt_l,  g_Wgt_l);
    cudaGetSymbolAddress((void**)&Wdtt_h, g_Wdtt_h); cudaGetSymbolAddress((void**)&Wdtt_l, g_Wdtt_l);
    cudaGetSymbolAddress((void**)&Wot_h,  g_Wot_h);  cudaGetSymbolAddress((void**)&Wot_l,  g_Wot_l);

    cudaFuncSetAttribute((const void*)gemm_mma<0>, cudaFuncAttributeMaxDynamicSharedMemorySize, GEMM_SMEM);
    cudaFuncSetAttribute((const void*)gemm_mma<1>, cudaFuncAttributeMaxDynamicSharedMemorySize, GEMM_SMEM);
    cudaFuncSetAttribute((const void*)gemm_mma<2>, cudaFuncAttributeMaxDynamicSharedMemorySize, GEMM_SMEM);

    dim3 tg(32, 32);
    dim3 tb(32, 8);
    tsplit_kernel<<<tg, tb>>>(Win,  Wint_h, Wint_l);
    tsplit_kernel<<<tg, tb>>>(Wg,   Wgt_h,  Wgt_l);
    tsplit_kernel<<<tg, tb>>>(Wdt,  Wdtt_h, Wdtt_l);
    tsplit_kernel<<<tg, tb>>>(Wout, Wot_h,  Wot_l);
    split_kernel<<<2048, 256>>>(u, uh, ul, MM * DD / 4);

    dim3 gg(DD / GBN, MM / GBM);  // (8, 32)
    gemm_mma<0><<<gg, 256, GEMM_SMEM>>>(uh, ul, Wint_h, Wint_l, b_in, x1);
    gemm_mma<1><<<gg, 256, GEMM_SMEM>>>(uh, ul, Wgt_h,  Wgt_l,  bg,   zb);
    conv_silu_kernel<<<2048, 256>>>(x1, convw, convb, x3, x3h, x3l);
    gemm_mma<2><<<gg, 256, GEMM_SMEM>>>(x3h, x3l, Wdtt_h, Wdtt_l, bdt, dtb);
    proj_bc_kernel<<<MM / 32, 256>>>(x3, Wb, Wc, bb, bc, Bmb, Cmb);
    scan_kernel<<<BB * (DD / 8), 128>>>(dtb, x3, Bmb, Cmb, A, zb, yh, yl);
    gemm_mma<0><<<gg, 256, GEMM_SMEM>>>(yh, yl, Wot_h, Wot_l, bout, out);
}